// round 3
// baseline (speedup 1.0000x reference)
#include <cuda_runtime.h>
#include <math.h>

#define BATCH  16
#define NPTS   8192
#define NPOINT 2048
#define KNN    16
#define CIN    64
#define COUT   128

// ---------------- scratch (static device globals; no allocation allowed) ----
__device__ float  g_h[(size_t)BATCH * NPTS * COUT];      // conv output, 64 MB
__device__ int    g_knn[(size_t)BATCH * NPOINT * KNN];   // kNN indices
__device__ double g_psum[128 * COUT];                    // stats partials
__device__ double g_psq [128 * COUT];
__device__ float  g_scale[COUT];
__device__ float  g_shift[COUT];

// ---------------------------------------------------------------- FPS ------
// One CTA per batch; points resident in registers (8/thread x 1024 threads).
// Per iteration:
//   - update dist[k] = min(dist[k], ||p-c||^2), local argmax (first max)
//   - warp butterfly argmax (tie -> lower index), lane0 publishes to smem
//   - barrier; ALL warps redundantly reduce the 32 warp maxima, so every
//     thread learns `farthest`; the owner thread publishes centroid coords
//   - barrier; next iteration reads coords from smem
// Exactly matches jnp semantics: centroid recorded BEFORE update; argmax is
// first-occurrence on ties.
__global__ __launch_bounds__(1024, 1)
void fps_kernel(const float* __restrict__ xyz, float* __restrict__ out_xyz)
{
    __shared__ float rv[32];
    __shared__ int   ri[32];
    __shared__ float scx, scy, scz;

    const int b   = blockIdx.x;
    const int tid = threadIdx.x;
    const int lane = tid & 31;

    const float* base = xyz + (size_t)b * NPTS * 3;

    float px[8], py[8], pz[8], dist[8];
#pragma unroll
    for (int k = 0; k < 8; k++) {
        int p = tid + k * 1024;
        px[k] = base[3 * p + 0];
        py[k] = base[3 * p + 1];
        pz[k] = base[3 * p + 2];
        dist[k] = 1e10f;
    }

    // initial centroid = point 0
    if (tid == 0) { scx = base[0]; scy = base[1]; scz = base[2]; }
    __syncthreads();

    float* oxyz = out_xyz + (size_t)b * NPOINT * 3;

    for (int i = 0; i < NPOINT; i++) {
        const float cx = scx, cy = scy, cz = scz;
        if (tid == 0) {
            oxyz[i * 3 + 0] = cx;
            oxyz[i * 3 + 1] = cy;
            oxyz[i * 3 + 2] = cz;
        }
        float bv = -1.0f; int bi = 0;
#pragma unroll
        for (int k = 0; k < 8; k++) {
            float dx = px[k] - cx, dy = py[k] - cy, dz = pz[k] - cz;
            float d = dx * dx;
            d = fmaf(dy, dy, d);
            d = fmaf(dz, dz, d);
            float nd = fminf(dist[k], d);
            dist[k] = nd;
            if (nd > bv) { bv = nd; bi = tid + k * 1024; }  // k ascending -> first max
        }
        // warp butterfly argmax: higher value wins, tie -> lower index
#pragma unroll
        for (int off = 16; off > 0; off >>= 1) {
            float ov = __shfl_xor_sync(0xffffffffu, bv, off);
            int   oi = __shfl_xor_sync(0xffffffffu, bi, off);
            if (ov > bv || (ov == bv && oi < bi)) { bv = ov; bi = oi; }
        }
        if (lane == 0) { rv[tid >> 5] = bv; ri[tid >> 5] = bi; }
        __syncthreads();

        // every warp redundantly reduces the 32 candidates -> all threads know winner
        float fv = rv[lane]; int fi = ri[lane];
#pragma unroll
        for (int off = 16; off > 0; off >>= 1) {
            float ov = __shfl_xor_sync(0xffffffffu, fv, off);
            int   oi = __shfl_xor_sync(0xffffffffu, fi, off);
            if (ov > fv || (ov == fv && oi < fi)) { fv = ov; fi = oi; }
        }
        // owner thread publishes next centroid's coordinates from registers
        if (tid == (fi & 1023)) {
            const int kk = fi >> 10;
#pragma unroll
            for (int k = 0; k < 8; k++) {
                if (k == kk) { scx = px[k]; scy = py[k]; scz = pz[k]; }
            }
        }
        __syncthreads();
    }
}

// ---------------------------------------------------------------- kNN ------
// 128 blocks x 256 threads; one query per thread; candidate tiles in SMEM.
// Per-thread sorted top-16 (ascending dist); strict '<' insert + stable shift
// reproduces lax.top_k's lowest-index-on-tie set (order irrelevant: max-pool).
#define TS 2048

__global__ __launch_bounds__(256)
void knn_kernel(const float* __restrict__ xyz,
                const float* __restrict__ new_xyz,
                int* __restrict__ knn_out)
{
    __shared__ float sx[TS], sy[TS], sz[TS];
    const int b = blockIdx.x >> 3;
    const int q = ((blockIdx.x & 7) << 8) + threadIdx.x;

    const float* nb = new_xyz + ((size_t)b * NPOINT + q) * 3;
    const float qx = nb[0], qy = nb[1], qz = nb[2];

    float kd[KNN]; int ki[KNN];
#pragma unroll
    for (int k = 0; k < KNN; k++) { kd[k] = 3.4e38f; ki[k] = -1; }
    float worst = 3.4e38f;

    const float* base = xyz + (size_t)b * NPTS * 3;
    for (int t = 0; t < NPTS; t += TS) {
        __syncthreads();
        for (int j = threadIdx.x; j < TS * 3; j += 256) {
            float v = base[t * 3 + j];
            int p = j / 3, d = j - 3 * p;
            (d == 0 ? sx : (d == 1 ? sy : sz))[p] = v;
        }
        __syncthreads();
        for (int j = 0; j < TS; j++) {
            float dx = qx - sx[j], dy = qy - sy[j], dz = qz - sz[j];
            float d = dx * dx;
            d = fmaf(dy, dy, d);
            d = fmaf(dz, dz, d);
            if (d < worst) {
                int pos = KNN - 1;
#pragma unroll
                for (int s = KNN - 1; s > 0; s--) {
                    if (pos == s && kd[s - 1] > d) {
                        kd[s] = kd[s - 1]; ki[s] = ki[s - 1]; pos = s - 1;
                    }
                }
                kd[pos] = d; ki[pos] = t + j;
                worst = kd[KNN - 1];
            }
        }
    }
    int* o = knn_out + ((size_t)b * NPOINT + q) * KNN;
#pragma unroll
    for (int k = 0; k < KNN; k++) o[k] = ki[k];
}

// ---------------------------------------------------------------- GEMM -----
// h[m, c] = sum_k feat[m, k] * W[c, k] + b[c].  W^T in SMEM (conflict-free),
// 4 rows x 4 channels per thread, FFMA-bound.
__global__ __launch_bounds__(256)
void gemm_kernel(const float* __restrict__ feat,
                 const float* __restrict__ W,
                 const float* __restrict__ bias,
                 float* __restrict__ h)
{
    __shared__ float Wt[CIN * COUT];   // Wt[k*128 + c]
    __shared__ float sf[32 * CIN];     // 32 rows of features
    const int tid = threadIdx.x;

    for (int j = tid; j < CIN * COUT; j += 256) {
        int c = j >> 6, k = j & 63;            // W row-major [c][k]
        Wt[k * COUT + c] = W[j];
    }
    const size_t row0 = (size_t)blockIdx.x * 32;
    const float* fb = feat + row0 * CIN;
    for (int j = tid; j < 32 * CIN; j += 256) sf[j] = fb[j];
    __syncthreads();

    const int cg = tid & 31;   // channels cg*4 .. cg*4+3
    const int rg = tid >> 5;   // rows rg*4 .. rg*4+3

    float acc[4][4];
#pragma unroll
    for (int r = 0; r < 4; r++)
#pragma unroll
        for (int c = 0; c < 4; c++) acc[r][c] = 0.0f;

#pragma unroll 8
    for (int k = 0; k < CIN; k++) {
        float4 wv = *(const float4*)&Wt[k * COUT + cg * 4];
        float f0 = sf[(rg * 4 + 0) * CIN + k];
        float f1 = sf[(rg * 4 + 1) * CIN + k];
        float f2 = sf[(rg * 4 + 2) * CIN + k];
        float f3 = sf[(rg * 4 + 3) * CIN + k];
        acc[0][0] = fmaf(f0, wv.x, acc[0][0]);
        acc[0][1] = fmaf(f0, wv.y, acc[0][1]);
        acc[0][2] = fmaf(f0, wv.z, acc[0][2]);
        acc[0][3] = fmaf(f0, wv.w, acc[0][3]);
        acc[1][0] = fmaf(f1, wv.x, acc[1][0]);
        acc[1][1] = fmaf(f1, wv.y, acc[1][1]);
        acc[1][2] = fmaf(f1, wv.z, acc[1][2]);
        acc[1][3] = fmaf(f1, wv.w, acc[1][3]);
        acc[2][0] = fmaf(f2, wv.x, acc[2][0]);
        acc[2][1] = fmaf(f2, wv.y, acc[2][1]);
        acc[2][2] = fmaf(f2, wv.z, acc[2][2]);
        acc[2][3] = fmaf(f2, wv.w, acc[2][3]);
        acc[3][0] = fmaf(f3, wv.x, acc[3][0]);
        acc[3][1] = fmaf(f3, wv.y, acc[3][1]);
        acc[3][2] = fmaf(f3, wv.z, acc[3][2]);
        acc[3][3] = fmaf(f3, wv.w, acc[3][3]);
    }
    const float4 bb = *(const float4*)&bias[cg * 4];
#pragma unroll
    for (int r = 0; r < 4; r++) {
        float4 o;
        o.x = acc[r][0] + bb.x;
        o.y = acc[r][1] + bb.y;
        o.z = acc[r][2] + bb.z;
        o.w = acc[r][3] + bb.w;
        *(float4*)&h[(row0 + rg * 4 + r) * COUT + cg * 4] = o;
    }
}

// ----------------------------------------------------------- BN stats ------
// Deterministic two-stage fp64 reduction (no atomics -> bitwise deterministic).
__global__ __launch_bounds__(128)
void stats_kernel(const float* __restrict__ h)
{
    const int c = threadIdx.x;
    const size_t r0 = (size_t)blockIdx.x * 1024;
    double s = 0.0, ss = 0.0;
    const float* p = h + r0 * COUT + c;
    for (int r = 0; r < 1024; r++) {
        double v = (double)p[(size_t)r * COUT];
        s += v; ss += v * v;
    }
    g_psum[blockIdx.x * COUT + c] = s;
    g_psq [blockIdx.x * COUT + c] = ss;
}

__global__ __launch_bounds__(128)
void finalize_kernel(const float* __restrict__ gamma, const float* __restrict__ beta)
{
    const int c = threadIdx.x;
    double s = 0.0, ss = 0.0;
    for (int blk = 0; blk < 128; blk++) {
        s  += g_psum[blk * COUT + c];
        ss += g_psq [blk * COUT + c];
    }
    const double inv_n = 1.0 / (double)((size_t)BATCH * NPTS);
    double mean = s * inv_n;
    double var  = ss * inv_n - mean * mean;
    double scale = (double)gamma[c] / sqrt(var + 1e-5);
    g_scale[c] = (float)scale;
    g_shift[c] = (float)((double)beta[c] - mean * scale);
}

// -------------------------------------------------- gather + maxpool -------
// relu(max(...)) == max(relu(...)) (monotone); BN fused via scale/shift.
__global__ __launch_bounds__(128)
void maxpool_kernel(const float* __restrict__ h,
                    const int* __restrict__ knn,
                    float* __restrict__ out_feat)
{
    __shared__ int sidx[KNN];
    const int b = blockIdx.x >> 11;
    const int q = blockIdx.x & 2047;
    const int c = threadIdx.x;
    if (c < KNN) sidx[c] = knn[((size_t)b * NPOINT + q) * KNN + c];
    __syncthreads();

    const float sc = g_scale[c], sh = g_shift[c];
    const float* hb = h + (size_t)b * NPTS * COUT;
    float m = -3.4e38f;
#pragma unroll
    for (int k = 0; k < KNN; k++) {
        float v = hb[(size_t)sidx[k] * COUT + c];
        m = fmaxf(m, fmaf(v, sc, sh));
    }
    m = fmaxf(m, 0.0f);
    out_feat[((size_t)b * NPOINT + q) * COUT + c] = m;
}

// ---------------------------------------------------------------------------
extern "C" void kernel_launch(void* const* d_in, const int* in_sizes, int n_in,
                              void* d_out, int out_size)
{
    const float* xyz   = (const float*)d_in[0];
    const float* feat  = (const float*)d_in[1];
    const float* W     = (const float*)d_in[2];
    const float* bias  = (const float*)d_in[3];
    const float* gamma = (const float*)d_in[4];
    const float* beta  = (const float*)d_in[5];

    float* out      = (float*)d_out;
    float* out_xyz  = out;
    float* out_feat = out + ((size_t)out_size - (size_t)BATCH * NPOINT * COUT);

    fps_kernel<<<BATCH, 1024>>>(xyz, out_xyz);
    gemm_kernel<<<(BATCH * NPTS) / 32, 256>>>(feat, W, bias, g_h);
    knn_kernel<<<BATCH * 8, 256>>>(xyz, out_xyz, g_knn);
    stats_kernel<<<128, 128>>>(g_h);
    finalize_kernel<<<1, 128>>>(gamma, beta);
    maxpool_kernel<<<BATCH * NPOINT, 128>>>(g_h, g_knn, out_feat);
    (void)n_in; (void)in_sizes;
}

// round 4
// speedup vs baseline: 1.1381x; 1.1381x over previous
#include <cuda_runtime.h>
#include <math.h>

#define BATCH  16
#define NPTS   8192
#define NPOINT 2048
#define KNN    16
#define CIN    64
#define COUT   128

// ---------------- scratch (static device globals; no allocation allowed) ----
__device__ float  g_h[(size_t)BATCH * NPTS * COUT];      // conv output, 64 MB
__device__ int    g_knn[(size_t)BATCH * NPOINT * KNN];   // kNN indices
__device__ float  g_fsum[1024 * COUT];                   // stats partials (fp32 tree)
__device__ float  g_fsq [1024 * COUT];
__device__ float  g_scale[COUT];
__device__ float  g_shift[COUT];

// ---------------------------------------------------------------- FPS ------
// One CTA per batch; point coords in registers (8/thread x 1024 threads) AND
// mirrored in SMEM (for centroid fetch). Per iteration:
//   update dists -> per-thread argmax -> REDUX warp argmax -> lane0 STS ->
//   ONE barrier -> all warps redundantly REDUX-reduce the 32 warp winners ->
//   every thread knows `far`; coords read from SMEM next iteration.
// Tie rule everywhere: max value, then MIN index (first occurrence) — exactly
// jnp.argmax. Distance formula identical to reference contraction (sub/mul/fma),
// so fp32 values are bit-identical and the argmax sequence matches.
#define FPS_SMEM_BYTES (3 * NPTS * 4 + 2 * 32 * 4 + 2 * 32 * 4)

__global__ __launch_bounds__(1024, 1)
void fps_kernel(const float* __restrict__ xyz, float* __restrict__ out_xyz)
{
    extern __shared__ float smem[];
    float*    sx = smem;
    float*    sy = sx + NPTS;
    float*    sz = sy + NPTS;
    unsigned* wv = (unsigned*)(sz + NPTS);   // [2][32] double-buffered warp maxima
    int*      wi = (int*)(wv + 64);          // [2][32] warp argmax indices

    const int b    = blockIdx.x;
    const int tid  = threadIdx.x;
    const int lane = tid & 31;
    const int warp = tid >> 5;

    const float* base = xyz + (size_t)b * NPTS * 3;
    for (int j = tid; j < NPTS * 3; j += 1024) {
        float v = base[j];
        int p = j / 3, d = j - 3 * p;
        (d == 0 ? sx : (d == 1 ? sy : sz))[p] = v;
    }
    __syncthreads();

    float px[8], py[8], pz[8], dist[8];
#pragma unroll
    for (int k = 0; k < 8; k++) {
        int p = tid + k * 1024;
        px[k] = sx[p]; py[k] = sy[p]; pz[k] = sz[p];
        dist[k] = 1e10f;
    }

    int far = 0;
    float* oxyz = out_xyz + (size_t)b * NPOINT * 3;

    for (int i = 0; i < NPOINT; i++) {
        const float cx = sx[far], cy = sy[far], cz = sz[far];
        if (tid == 0) {
            oxyz[i * 3 + 0] = cx;
            oxyz[i * 3 + 1] = cy;
            oxyz[i * 3 + 2] = cz;
        }
        float bv = -1.0f; int bi = 0;
#pragma unroll
        for (int k = 0; k < 8; k++) {
            float dx = px[k] - cx, dy = py[k] - cy, dz = pz[k] - cz;
            float d = dx * dx;
            d = fmaf(dy, dy, d);
            d = fmaf(dz, dz, d);
            float nd = fminf(dist[k], d);
            dist[k] = nd;
            if (nd > bv) { bv = nd; bi = tid + k * 1024; }  // k ascending -> first max
        }
        // warp argmax via REDUX: dist >= 0 so float order == unsigned-bits order
        unsigned vb   = __float_as_uint(bv);
        unsigned wmax = __reduce_max_sync(0xffffffffu, vb);
        unsigned cand = (vb == wmax) ? (unsigned)bi : 0x7fffffffu;
        unsigned widx = __reduce_min_sync(0xffffffffu, cand);

        const int buf = (i & 1) * 32;
        if (lane == 0) { wv[buf + warp] = wmax; wi[buf + warp] = (int)widx; }
        __syncthreads();

        // every warp redundantly reduces the 32 warp winners (conflict-free LDS)
        unsigned v2   = wv[buf + lane];
        unsigned i2   = (unsigned)wi[buf + lane];
        unsigned gmax = __reduce_max_sync(0xffffffffu, v2);
        unsigned c2   = (v2 == gmax) ? i2 : 0x7fffffffu;
        far = (int)__reduce_min_sync(0xffffffffu, c2);
    }
}

// ---------------------------------------------------------------- kNN ------
// 128 blocks x 256 threads; one query per thread; candidate tiles in SMEM.
// Per-thread sorted top-16; strict '<' insert + stable shift reproduces
// lax.top_k's lowest-index-on-tie set (order irrelevant: max-pool follows).
#define TS 2048

__global__ __launch_bounds__(256)
void knn_kernel(const float* __restrict__ xyz,
                const float* __restrict__ new_xyz,
                int* __restrict__ knn_out)
{
    __shared__ float sx[TS], sy[TS], sz[TS];
    const int b = blockIdx.x >> 3;
    const int q = ((blockIdx.x & 7) << 8) + threadIdx.x;

    const float* nb = new_xyz + ((size_t)b * NPOINT + q) * 3;
    const float qx = nb[0], qy = nb[1], qz = nb[2];

    float kd[KNN]; int ki[KNN];
#pragma unroll
    for (int k = 0; k < KNN; k++) { kd[k] = 3.4e38f; ki[k] = -1; }
    float worst = 3.4e38f;

    const float* base = xyz + (size_t)b * NPTS * 3;
    for (int t = 0; t < NPTS; t += TS) {
        __syncthreads();
        for (int j = threadIdx.x; j < TS * 3; j += 256) {
            float v = base[t * 3 + j];
            int p = j / 3, d = j - 3 * p;
            (d == 0 ? sx : (d == 1 ? sy : sz))[p] = v;
        }
        __syncthreads();
        for (int j = 0; j < TS; j++) {
            float dx = qx - sx[j], dy = qy - sy[j], dz = qz - sz[j];
            float d = dx * dx;
            d = fmaf(dy, dy, d);
            d = fmaf(dz, dz, d);
            if (d < worst) {
                int pos = KNN - 1;
#pragma unroll
                for (int s = KNN - 1; s > 0; s--) {
                    if (pos == s && kd[s - 1] > d) {
                        kd[s] = kd[s - 1]; ki[s] = ki[s - 1]; pos = s - 1;
                    }
                }
                kd[pos] = d; ki[pos] = t + j;
                worst = kd[KNN - 1];
            }
        }
    }
    int* o = knn_out + ((size_t)b * NPOINT + q) * KNN;
#pragma unroll
    for (int k = 0; k < KNN; k++) o[k] = ki[k];
}

// ---------------------------------------------------------------- GEMM -----
// h[m, c] = sum_k feat[m, k] * W[c, k] + b[c].  W^T in SMEM (conflict-free),
// 4 rows x 4 channels per thread, FFMA-bound.
__global__ __launch_bounds__(256)
void gemm_kernel(const float* __restrict__ feat,
                 const float* __restrict__ W,
                 const float* __restrict__ bias,
                 float* __restrict__ h)
{
    __shared__ float Wt[CIN * COUT];   // Wt[k*128 + c]
    __shared__ float sf[32 * CIN];     // 32 rows of features
    const int tid = threadIdx.x;

    for (int j = tid; j < CIN * COUT; j += 256) {
        int c = j >> 6, k = j & 63;            // W row-major [c][k]
        Wt[k * COUT + c] = W[j];
    }
    const size_t row0 = (size_t)blockIdx.x * 32;
    const float* fb = feat + row0 * CIN;
    for (int j = tid; j < 32 * CIN; j += 256) sf[j] = fb[j];
    __syncthreads();

    const int cg = tid & 31;   // channels cg*4 .. cg*4+3
    const int rg = tid >> 5;   // rows rg*4 .. rg*4+3

    float acc[4][4];
#pragma unroll
    for (int r = 0; r < 4; r++)
#pragma unroll
        for (int c = 0; c < 4; c++) acc[r][c] = 0.0f;

#pragma unroll 8
    for (int k = 0; k < CIN; k++) {
        float4 wv = *(const float4*)&Wt[k * COUT + cg * 4];
        float f0 = sf[(rg * 4 + 0) * CIN + k];
        float f1 = sf[(rg * 4 + 1) * CIN + k];
        float f2 = sf[(rg * 4 + 2) * CIN + k];
        float f3 = sf[(rg * 4 + 3) * CIN + k];
        acc[0][0] = fmaf(f0, wv.x, acc[0][0]);
        acc[0][1] = fmaf(f0, wv.y, acc[0][1]);
        acc[0][2] = fmaf(f0, wv.z, acc[0][2]);
        acc[0][3] = fmaf(f0, wv.w, acc[0][3]);
        acc[1][0] = fmaf(f1, wv.x, acc[1][0]);
        acc[1][1] = fmaf(f1, wv.y, acc[1][1]);
        acc[1][2] = fmaf(f1, wv.z, acc[1][2]);
        acc[1][3] = fmaf(f1, wv.w, acc[1][3]);
        acc[2][0] = fmaf(f2, wv.x, acc[2][0]);
        acc[2][1] = fmaf(f2, wv.y, acc[2][1]);
        acc[2][2] = fmaf(f2, wv.z, acc[2][2]);
        acc[2][3] = fmaf(f2, wv.w, acc[2][3]);
        acc[3][0] = fmaf(f3, wv.x, acc[3][0]);
        acc[3][1] = fmaf(f3, wv.y, acc[3][1]);
        acc[3][2] = fmaf(f3, wv.z, acc[3][2]);
        acc[3][3] = fmaf(f3, wv.w, acc[3][3]);
    }
    const float4 bb = *(const float4*)&bias[cg * 4];
#pragma unroll
    for (int r = 0; r < 4; r++) {
        float4 o;
        o.x = acc[r][0] + bb.x;
        o.y = acc[r][1] + bb.y;
        o.z = acc[r][2] + bb.z;
        o.w = acc[r][3] + bb.w;
        *(float4*)&h[(row0 + rg * 4 + r) * COUT + cg * 4] = o;
    }
}

// ----------------------------------------------------------- BN stats ------
// 1024 CTAs x 256 threads; float4 coalesced loads; fixed-order fp32 tree:
// 16 values/thread -> 8-way SMEM reduce -> fp32 partial per (CTA, channel).
// Deterministic (no atomics, fixed order). fp64 4-way ILP in finalize.
__global__ __launch_bounds__(256)
void stats_kernel(const float* __restrict__ h)
{
    __shared__ float4 reds[8][32];
    __shared__ float4 redq[8][32];
    const int tid = threadIdx.x;
    const int cg  = tid & 31;     // channel float4 group
    const int r   = tid >> 5;     // 0..7

    const float* p = h + ((size_t)blockIdx.x * 128 + r) * COUT + cg * 4;
    float4 s = make_float4(0.f, 0.f, 0.f, 0.f);
    float4 q = make_float4(0.f, 0.f, 0.f, 0.f);
#pragma unroll
    for (int it = 0; it < 16; it++) {
        float4 v = *(const float4*)(p + (size_t)it * 8 * COUT);
        s.x += v.x; s.y += v.y; s.z += v.z; s.w += v.w;
        q.x = fmaf(v.x, v.x, q.x);
        q.y = fmaf(v.y, v.y, q.y);
        q.z = fmaf(v.z, v.z, q.z);
        q.w = fmaf(v.w, v.w, q.w);
    }
    reds[r][cg] = s;
    redq[r][cg] = q;
    __syncthreads();
    if (r == 0) {
        float4 ts = reds[0][cg], tq = redq[0][cg];
#pragma unroll
        for (int j = 1; j < 8; j++) {
            float4 a = reds[j][cg], b2 = redq[j][cg];
            ts.x += a.x; ts.y += a.y; ts.z += a.z; ts.w += a.w;
            tq.x += b2.x; tq.y += b2.y; tq.z += b2.z; tq.w += b2.w;
        }
        *(float4*)&g_fsum[(size_t)blockIdx.x * COUT + cg * 4] = ts;
        *(float4*)&g_fsq [(size_t)blockIdx.x * COUT + cg * 4] = tq;
    }
}

__global__ __launch_bounds__(128)
void finalize_kernel(const float* __restrict__ gamma, const float* __restrict__ beta)
{
    const int c = threadIdx.x;
    double s0 = 0, s1 = 0, s2 = 0, s3 = 0;
    double q0 = 0, q1 = 0, q2 = 0, q3 = 0;
    for (int blk = 0; blk < 1024; blk += 4) {
        s0 += (double)g_fsum[(blk + 0) * COUT + c];
        s1 += (double)g_fsum[(blk + 1) * COUT + c];
        s2 += (double)g_fsum[(blk + 2) * COUT + c];
        s3 += (double)g_fsum[(blk + 3) * COUT + c];
        q0 += (double)g_fsq [(blk + 0) * COUT + c];
        q1 += (double)g_fsq [(blk + 1) * COUT + c];
        q2 += (double)g_fsq [(blk + 2) * COUT + c];
        q3 += (double)g_fsq [(blk + 3) * COUT + c];
    }
    double s = (s0 + s1) + (s2 + s3);
    double q = (q0 + q1) + (q2 + q3);
    const double inv_n = 1.0 / (double)((size_t)BATCH * NPTS);
    double mean = s * inv_n;
    double var  = q * inv_n - mean * mean;
    double scale = (double)gamma[c] / sqrt(var + 1e-5);
    g_scale[c] = (float)scale;
    g_shift[c] = (float)((double)beta[c] - mean * scale);
}

// -------------------------------------------------- gather + maxpool -------
// relu(max(...)) == max(relu(...)) (monotone); BN fused via scale/shift.
__global__ __launch_bounds__(128)
void maxpool_kernel(const float* __restrict__ h,
                    const int* __restrict__ knn,
                    float* __restrict__ out_feat)
{
    __shared__ int sidx[KNN];
    const int b = blockIdx.x >> 11;
    const int q = blockIdx.x & 2047;
    const int c = threadIdx.x;
    if (c < KNN) sidx[c] = knn[((size_t)b * NPOINT + q) * KNN + c];
    __syncthreads();

    const float sc = g_scale[c], sh = g_shift[c];
    const float* hb = h + (size_t)b * NPTS * COUT;
    float m = -3.4e38f;
#pragma unroll
    for (int k = 0; k < KNN; k++) {
        float v = hb[(size_t)sidx[k] * COUT + c];
        m = fmaxf(m, fmaf(v, sc, sh));
    }
    m = fmaxf(m, 0.0f);
    out_feat[((size_t)b * NPOINT + q) * COUT + c] = m;
}

// ---------------------------------------------------------------------------
extern "C" void kernel_launch(void* const* d_in, const int* in_sizes, int n_in,
                              void* d_out, int out_size)
{
    const float* xyz   = (const float*)d_in[0];
    const float* feat  = (const float*)d_in[1];
    const float* W     = (const float*)d_in[2];
    const float* bias  = (const float*)d_in[3];
    const float* gamma = (const float*)d_in[4];
    const float* beta  = (const float*)d_in[5];

    float* out      = (float*)d_out;
    float* out_xyz  = out;
    float* out_feat = out + ((size_t)out_size - (size_t)BATCH * NPOINT * COUT);

    cudaFuncSetAttribute(fps_kernel, cudaFuncAttributeMaxDynamicSharedMemorySize,
                         FPS_SMEM_BYTES);

    fps_kernel<<<BATCH, 1024, FPS_SMEM_BYTES>>>(xyz, out_xyz);
    gemm_kernel<<<(BATCH * NPTS) / 32, 256>>>(feat, W, bias, g_h);
    knn_kernel<<<BATCH * 8, 256>>>(xyz, out_xyz, g_knn);
    stats_kernel<<<1024, 256>>>(g_h);
    finalize_kernel<<<1, 128>>>(gamma, beta);
    maxpool_kernel<<<BATCH * NPOINT, 128>>>(g_h, g_knn, out_feat);
    (void)n_in; (void)in_sizes;
}